// round 2
// baseline (speedup 1.0000x reference)
#include <cuda_runtime.h>

#define B_   64
#define L_   32
#define T_   31
#define V_   16000
#define ENC_ 512
#define DEC_ 512
#define ATT_ 512
#define EMB_ 256
#define P_   256

// ---------------- device scratch (no allocs allowed) ----------------
__device__ float g_state[B_ * 1024];            // [h(512) | c(512)] per row
__device__ float g_meanenc[B_ * ENC_];
__device__ float g_encflat[B_ * P_ * ENC_];     // enc[b][p][c]  (33.5 MB)
__device__ float g_att1[B_ * P_ * ATT_];        // enc@W_enc_att^T + b (33.5 MB)
__device__ float g_Wab[1024 * 512];             // [W_dec_att ; W_beta]
__device__ float g_bab[1024];
__device__ float g_Winit[1024 * 512];           // [W_init_h ; W_init_c]
__device__ float g_binit[1024];
__device__ float g_Wlstm[2048 * 1280];          // [W_ih | W_hh]
__device__ float g_blstm[2048];                 // b_ih + b_hh
__device__ float g_ab[B_ * 1024];               // att2 logits | beta logits
__device__ float g_xinh[B_ * 1280];             // [emb_t | gated awe | h]
__device__ float g_gates[B_ * 2048];

// ---------------- generic 64x64-tile SGEMM: C = A * W^T + bias ----------------
// A: [M x K] row-major (lda), W: [N x K] row-major (ldw), C: [M x N] (ldc).
// Grid fully tiles (N/64, M/64); K multiple of 16; all dims here are multiples.
// If lens != nullptr: row m is active iff t < lens[m]-1, else write 0 (masked fc).
__global__ __launch_bounds__(256) void gemm64_kernel(
    const float* __restrict__ A, int lda,
    const float* __restrict__ W, int ldw,
    const float* __restrict__ bias,
    float* __restrict__ C, int ldc,
    int K,
    const int* __restrict__ lens, int t)
{
    __shared__ __align__(16) float As[16][64];
    __shared__ __align__(16) float Ws[16][64];

    const int tid = threadIdx.x;
    const int m0 = blockIdx.y * 64;
    const int n0 = blockIdx.x * 64;
    const int lr = tid >> 2;          // 0..63 row in tile for loading
    const int lk = (tid & 3) << 2;    // 0,4,8,12
    const int tx = tid & 15;          // n group
    const int ty = tid >> 4;          // m group

    float acc[4][4];
#pragma unroll
    for (int i = 0; i < 4; i++)
#pragma unroll
        for (int j = 0; j < 4; j++) acc[i][j] = 0.f;

    const float* aptr = A + (size_t)(m0 + lr) * lda + lk;
    const float* wptr = W + (size_t)(n0 + lr) * ldw + lk;

    for (int k0 = 0; k0 < K; k0 += 16) {
        float4 av = *reinterpret_cast<const float4*>(aptr + k0);
        float4 wv = *reinterpret_cast<const float4*>(wptr + k0);
        As[lk + 0][lr] = av.x; As[lk + 1][lr] = av.y;
        As[lk + 2][lr] = av.z; As[lk + 3][lr] = av.w;
        Ws[lk + 0][lr] = wv.x; Ws[lk + 1][lr] = wv.y;
        Ws[lk + 2][lr] = wv.z; Ws[lk + 3][lr] = wv.w;
        __syncthreads();
#pragma unroll
        for (int kk = 0; kk < 16; kk++) {
            float4 a = *reinterpret_cast<const float4*>(&As[kk][ty << 2]);
            float4 b = *reinterpret_cast<const float4*>(&Ws[kk][tx << 2]);
            float ar[4] = {a.x, a.y, a.z, a.w};
            float br[4] = {b.x, b.y, b.z, b.w};
#pragma unroll
            for (int i = 0; i < 4; i++)
#pragma unroll
                for (int j = 0; j < 4; j++)
                    acc[i][j] = fmaf(ar[i], br[j], acc[i][j]);
        }
        __syncthreads();
    }

    const int n = n0 + (tx << 2);
    float4 bv;
    bv.x = bias[n + 0]; bv.y = bias[n + 1];
    bv.z = bias[n + 2]; bv.w = bias[n + 3];
#pragma unroll
    for (int i = 0; i < 4; i++) {
        const int m = m0 + (ty << 2) + i;
        bool active = true;
        if (lens) active = (t < lens[m] - 1);
        float4 outv;
        if (active) {
            outv.x = acc[i][0] + bv.x;
            outv.y = acc[i][1] + bv.y;
            outv.z = acc[i][2] + bv.z;
            outv.w = acc[i][3] + bv.w;
        } else {
            outv.x = outv.y = outv.z = outv.w = 0.f;
        }
        *reinterpret_cast<float4*>(&C[(size_t)m * ldc + n]) = outv;
    }
}

// ---------------- one-time prep kernels ----------------
__global__ void prep_weights_kernel(
    const float* __restrict__ Wdec, const float* __restrict__ bdec,
    const float* __restrict__ Wbeta, const float* __restrict__ bbeta,
    const float* __restrict__ Wih, const float* __restrict__ Whh,
    const float* __restrict__ bih, const float* __restrict__ bhh,
    const float* __restrict__ Winith, const float* __restrict__ binith,
    const float* __restrict__ Winitc, const float* __restrict__ binitc)
{
    const int stride = gridDim.x * blockDim.x;
    const int i0 = blockIdx.x * blockDim.x + threadIdx.x;
    for (int i = i0; i < 512 * 512; i += stride) {
        g_Wab[i] = Wdec[i];
        g_Wab[512 * 512 + i] = Wbeta[i];
        g_Winit[i] = Winith[i];
        g_Winit[512 * 512 + i] = Winitc[i];
    }
    for (int i = i0; i < 512; i += stride) {
        g_bab[i] = bdec[i];       g_bab[512 + i] = bbeta[i];
        g_binit[i] = binith[i];   g_binit[512 + i] = binitc[i];
    }
    for (int i = i0; i < 2048 * 1280; i += stride) {
        int nrow = i / 1280, k = i - nrow * 1280;
        g_Wlstm[i] = (k < 768) ? Wih[nrow * 768 + k] : Whh[nrow * 512 + (k - 768)];
    }
    for (int i = i0; i < 2048; i += stride) g_blstm[i] = bih[i] + bhh[i];
}

// encoder_out [b][c][p] -> g_encflat [b][p][c]
__global__ void transpose_enc_kernel(const float* __restrict__ EO)
{
    __shared__ float tile[32][33];
    const int b = blockIdx.z;
    const int c0 = blockIdx.y * 32;
    const int p0 = blockIdx.x * 32;
    const int tx = threadIdx.x, ty = threadIdx.y;
#pragma unroll
    for (int j = 0; j < 32; j += 8)
        tile[ty + j][tx] = EO[((size_t)b * ENC_ + (c0 + ty + j)) * P_ + p0 + tx];
    __syncthreads();
#pragma unroll
    for (int j = 0; j < 32; j += 8)
        g_encflat[((size_t)b * P_ + (p0 + ty + j)) * ENC_ + c0 + tx] = tile[tx][ty + j];
}

__global__ void meanenc_kernel(const float* __restrict__ EO)
{
    const int wg = (blockIdx.x * blockDim.x + threadIdx.x) >> 5; // global warp
    const int lane = threadIdx.x & 31;
    if (wg >= B_ * ENC_) return;
    const float* row = EO + (size_t)wg * P_;
    float s = 0.f;
    for (int p = lane; p < P_; p += 32) s += row[p];
#pragma unroll
    for (int o = 16; o; o >>= 1) s += __shfl_xor_sync(0xffffffffu, s, o);
    if (!lane) g_meanenc[wg] = s * (1.0f / P_);
}

// ---------------- per-step fused attention kernel ----------------
// One block per batch row b. Computes: energy e[p] (relu(att1+att2)·w + b),
// softmax alpha, awe[c] = sum_p alpha*enc, gated by sigmoid(beta logits),
// and assembles xinh = [emb_t | gated_awe | h].
__global__ __launch_bounds__(256) void attention_kernel(
    const float* __restrict__ EO, const float* __restrict__ emb,
    const int* __restrict__ caps, const float* __restrict__ wfull,
    const float* __restrict__ bfull, int t)
{
    __shared__ float att2s[512];
    __shared__ float ws[512];
    __shared__ float es[256];
    __shared__ float red[8];
    __shared__ float sval;

    const int b = blockIdx.x;
    const int tid = threadIdx.x, lane = tid & 31, warp = tid >> 5;

    att2s[tid] = g_ab[b * 1024 + tid];
    att2s[tid + 256] = g_ab[b * 1024 + tid + 256];
    ws[tid] = wfull[tid];
    ws[tid + 256] = wfull[tid + 256];
    __syncthreads();

    const float bf = bfull[0];
    // energies: one warp per p
    for (int p = warp; p < P_; p += 8) {
        const float* arow = g_att1 + ((size_t)b * P_ + p) * ATT_;
        float s = 0.f;
        for (int a = lane; a < ATT_; a += 32) {
            float v = arow[a] + att2s[a];
            v = fmaxf(v, 0.f);
            s = fmaf(v, ws[a], s);
        }
#pragma unroll
        for (int o = 16; o; o >>= 1) s += __shfl_xor_sync(0xffffffffu, s, o);
        if (!lane) es[p] = s + bf;
    }
    __syncthreads();

    // softmax over 256 (one value per thread)
    float v = es[tid];
    float mx = v;
#pragma unroll
    for (int o = 16; o; o >>= 1) mx = fmaxf(mx, __shfl_xor_sync(0xffffffffu, mx, o));
    if (!lane) red[warp] = mx;
    __syncthreads();
    if (tid == 0) {
        float mm = red[0];
#pragma unroll
        for (int i = 1; i < 8; i++) mm = fmaxf(mm, red[i]);
        sval = mm;
    }
    __syncthreads();
    float ex = __expf(v - sval);
    float s2 = ex;
#pragma unroll
    for (int o = 16; o; o >>= 1) s2 += __shfl_xor_sync(0xffffffffu, s2, o);
    if (!lane) red[warp] = s2;
    __syncthreads();
    if (tid == 0) {
        float ss = 0.f;
#pragma unroll
        for (int i = 0; i < 8; i++) ss += red[i];
        sval = ss;
    }
    __syncthreads();
    es[tid] = ex / sval;   // alpha
    __syncthreads();

    // awe[c] = sum_p alpha[p]*EO[b][c][p], gated; one warp per c
    for (int c = warp; c < ENC_; c += 8) {
        const float* eop = EO + ((size_t)b * ENC_ + c) * P_;
        float s = 0.f;
        for (int p = lane; p < P_; p += 32) s = fmaf(es[p], eop[p], s);
#pragma unroll
        for (int o = 16; o; o >>= 1) s += __shfl_xor_sync(0xffffffffu, s, o);
        if (!lane) {
            float gl = g_ab[b * 1024 + 512 + c];
            float gate = 1.f / (1.f + __expf(-gl));
            g_xinh[b * 1280 + 256 + c] = gate * s;
        }
    }

    // xinh: emb_t and h copies
    const int tok = caps[b * L_ + t];
    g_xinh[b * 1280 + tid] = emb[(size_t)tok * EMB_ + tid];
    g_xinh[b * 1280 + 768 + tid]       = g_state[b * 1024 + tid];
    g_xinh[b * 1280 + 768 + 256 + tid] = g_state[b * 1024 + 256 + tid];
}

// ---------------- LSTM cell ----------------
__global__ void lstm_cell_kernel()
{
    const int b = blockIdx.x, d = threadIdx.x;
    const float* g = g_gates + b * 2048;
    const float gi = g[d];
    const float gf = g[512 + d];
    const float gg = g[1024 + d];
    const float go = g[1536 + d];
    const float c = g_state[b * 1024 + 512 + d];
    const float si = 1.f / (1.f + __expf(-gi));
    const float sf = 1.f / (1.f + __expf(-gf));
    const float so = 1.f / (1.f + __expf(-go));
    const float c2 = sf * c + si * tanhf(gg);
    const float h2 = so * tanhf(c2);
    g_state[b * 1024 + d] = h2;
    g_state[b * 1024 + 512 + d] = c2;
}

// ---------------- launch ----------------
extern "C" void kernel_launch(void* const* d_in, const int* in_sizes, int n_in,
                              void* d_out, int out_size)
{
    const float* EO        = (const float*)d_in[0];   // [64,512,16,16]
    const int*   caps      = (const int*)  d_in[1];   // [64,32]
    const int*   lens      = (const int*)  d_in[2];   // [64]
    const float* W_enc_att = (const float*)d_in[3];
    const float* b_enc_att = (const float*)d_in[4];
    const float* W_dec_att = (const float*)d_in[5];
    const float* b_dec_att = (const float*)d_in[6];
    const float* w_full    = (const float*)d_in[7];
    const float* b_full    = (const float*)d_in[8];
    const float* emb       = (const float*)d_in[9];
    const float* W_ih      = (const float*)d_in[10];
    const float* W_hh      = (const float*)d_in[11];
    const float* b_ih      = (const float*)d_in[12];
    const float* b_hh      = (const float*)d_in[13];
    const float* W_init_h  = (const float*)d_in[14];
    const float* b_init_h  = (const float*)d_in[15];
    const float* W_init_c  = (const float*)d_in[16];
    const float* b_init_c  = (const float*)d_in[17];
    const float* W_beta    = (const float*)d_in[18];
    const float* b_beta    = (const float*)d_in[19];
    const float* W_fc      = (const float*)d_in[20];
    const float* b_fc      = (const float*)d_in[21];
    float* out = (float*)d_out;

    float *state, *meanenc, *encflat, *att1, *Wab, *bab, *Winit, *binit;
    float *Wlstm, *blstm, *ab, *xinh, *gates;
    cudaGetSymbolAddress((void**)&state,   g_state);
    cudaGetSymbolAddress((void**)&meanenc, g_meanenc);
    cudaGetSymbolAddress((void**)&encflat, g_encflat);
    cudaGetSymbolAddress((void**)&att1,    g_att1);
    cudaGetSymbolAddress((void**)&Wab,     g_Wab);
    cudaGetSymbolAddress((void**)&bab,     g_bab);
    cudaGetSymbolAddress((void**)&Winit,   g_Winit);
    cudaGetSymbolAddress((void**)&binit,   g_binit);
    cudaGetSymbolAddress((void**)&Wlstm,   g_Wlstm);
    cudaGetSymbolAddress((void**)&blstm,   g_blstm);
    cudaGetSymbolAddress((void**)&ab,      g_ab);
    cudaGetSymbolAddress((void**)&xinh,    g_xinh);
    cudaGetSymbolAddress((void**)&gates,   g_gates);

    // ---- one-time prep ----
    prep_weights_kernel<<<512, 256>>>(W_dec_att, b_dec_att, W_beta, b_beta,
                                      W_ih, W_hh, b_ih, b_hh,
                                      W_init_h, b_init_h, W_init_c, b_init_c);
    transpose_enc_kernel<<<dim3(8, 16, 64), dim3(32, 8)>>>(EO);
    meanenc_kernel<<<4096, 256>>>(EO);
    // h0|c0 = meanenc @ [W_init_h;W_init_c]^T + b
    gemm64_kernel<<<dim3(16, 1), 256>>>(meanenc, 512, Winit, 512, binit,
                                        state, 1024, 512, nullptr, 0);
    // att1 = encflat @ W_enc_att^T + b  : [16384 x 512]
    gemm64_kernel<<<dim3(8, 256), 256>>>(encflat, 512, W_enc_att, 512, b_enc_att,
                                         att1, 512, 512, nullptr, 0);

    // ---- 31 sequential decode steps ----
    for (int t = 0; t < T_; t++) {
        // att2 | beta logits = h @ [W_dec_att;W_beta]^T + b
        gemm64_kernel<<<dim3(16, 1), 256>>>(state, 1024, Wab, 512, bab,
                                            ab, 1024, 512, nullptr, 0);
        // attention + softmax + gated awe + assemble xinh
        attention_kernel<<<64, 256>>>(EO, emb, caps, w_full, b_full, t);
        // gates = [xin|h] @ [W_ih|W_hh]^T + (b_ih+b_hh)
        gemm64_kernel<<<dim3(32, 1), 256>>>(xinh, 1280, Wlstm, 1280, blstm,
                                            gates, 2048, 1280, nullptr, 0);
        lstm_cell_kernel<<<64, 512>>>();
        // pred = h2 @ W_fc^T + b_fc (masked; zeros for finished captions)
        gemm64_kernel<<<dim3(250, 1), 256>>>(state, 1024, W_fc, 512, b_fc,
                                             out + (size_t)t * V_, T_ * V_,
                                             512, lens, t);
    }
}

// round 3
// speedup vs baseline: 2.2975x; 2.2975x over previous
#include <cuda_runtime.h>

#define B_   64
#define L_   32
#define T_   31
#define V_   16000
#define ENC_ 512
#define DEC_ 512
#define ATT_ 512
#define EMB_ 256
#define P_   256

#define AB_KSPLIT 8     // att2 GEMM: K=512 -> 8 x 64
#define G_KSPLIT  10    // gates GEMM: K=1280 -> 10 x 128

// ---------------- device scratch (no allocs allowed) ----------------
__device__ float g_state[B_ * 1024];            // [h(512) | c(512)] per row
__device__ float g_meanenc[B_ * ENC_];
__device__ float g_encflat[B_ * P_ * ENC_];     // enc[b][p][c]
__device__ float g_att1[B_ * P_ * ATT_];        // enc@W_enc_att^T + b
__device__ float g_Wab[1024 * 512];             // [W_dec_att ; W_beta]
__device__ float g_bab[1024];
__device__ float g_Winit[1024 * 512];           // [W_init_h ; W_init_c]
__device__ float g_binit[1024];
__device__ float g_Wlstm[2048 * 1280];          // [W_ih | W_hh]
__device__ float g_blstm[2048];                 // b_ih + b_hh
__device__ float g_xinh[B_ * 1280];             // [emb_t | gated awe | h]
__device__ float g_abp[AB_KSPLIT * B_ * 1024];  // att2|beta split-K partials
__device__ float g_gp[G_KSPLIT * B_ * 2048];    // gates split-K partials
__device__ float g_hall[T_ * B_ * DEC_];        // h2 snapshot per (t,b)
__device__ int   g_list[T_ * B_];               // active rows: v = t*64+b
__device__ int   g_nact;

// ============ big GEMM: 64x128 tile, double-buffered, C = A*W^T + bias ======
__global__ __launch_bounds__(256) void gemm_big_kernel(
    const float* __restrict__ A, int lda,
    const float* __restrict__ W, int ldw,
    const float* __restrict__ bias,
    float* __restrict__ C, int ldc, int K)
{
    __shared__ float As[2][16][68];
    __shared__ float Bs[2][16][136];

    const int tid = threadIdx.x;
    const int tx = tid & 15;        // n-group
    const int ty = tid >> 4;        // m-group (0..15)
    const int m0 = blockIdx.y * 64;
    const int n0 = blockIdx.x * 128;
    const int lr = tid >> 2;        // 0..63
    const int lk = (tid & 3) << 2;  // 0,4,8,12

    const float* aP  = A + (size_t)(m0 + lr) * lda + lk;
    const float* bP0 = W + (size_t)(n0 + lr) * ldw + lk;
    const float* bP1 = W + (size_t)(n0 + 64 + lr) * ldw + lk;

    float acc[4][8];
#pragma unroll
    for (int i = 0; i < 4; i++)
#pragma unroll
        for (int j = 0; j < 8; j++) acc[i][j] = 0.f;

    const int nsl = K >> 4;
    float4 a  = *reinterpret_cast<const float4*>(aP);
    float4 b0 = *reinterpret_cast<const float4*>(bP0);
    float4 b1 = *reinterpret_cast<const float4*>(bP1);
    {
        float ar[4] = {a.x, a.y, a.z, a.w};
        float br0[4] = {b0.x, b0.y, b0.z, b0.w};
        float br1[4] = {b1.x, b1.y, b1.z, b1.w};
#pragma unroll
        for (int j = 0; j < 4; j++) {
            As[0][lk + j][lr] = ar[j];
            Bs[0][lk + j][lr] = br0[j];
            Bs[0][lk + j][64 + lr] = br1[j];
        }
    }
    __syncthreads();

    int buf = 0;
    for (int s = 0; s < nsl; s++) {
        if (s + 1 < nsl) {
            a  = *reinterpret_cast<const float4*>(aP  + (s + 1) * 16);
            b0 = *reinterpret_cast<const float4*>(bP0 + (s + 1) * 16);
            b1 = *reinterpret_cast<const float4*>(bP1 + (s + 1) * 16);
        }
#pragma unroll
        for (int kk = 0; kk < 16; kk++) {
            float4 av  = *reinterpret_cast<const float4*>(&As[buf][kk][ty << 2]);
            float4 bv0 = *reinterpret_cast<const float4*>(&Bs[buf][kk][tx << 2]);
            float4 bv1 = *reinterpret_cast<const float4*>(&Bs[buf][kk][64 + (tx << 2)]);
            float ar[4] = {av.x, av.y, av.z, av.w};
            float br[8] = {bv0.x, bv0.y, bv0.z, bv0.w, bv1.x, bv1.y, bv1.z, bv1.w};
#pragma unroll
            for (int i = 0; i < 4; i++)
#pragma unroll
                for (int j = 0; j < 8; j++)
                    acc[i][j] = fmaf(ar[i], br[j], acc[i][j]);
        }
        if (s + 1 < nsl) {
            int nb = buf ^ 1;
            float ar[4] = {a.x, a.y, a.z, a.w};
            float br0[4] = {b0.x, b0.y, b0.z, b0.w};
            float br1[4] = {b1.x, b1.y, b1.z, b1.w};
#pragma unroll
            for (int j = 0; j < 4; j++) {
                As[nb][lk + j][lr] = ar[j];
                Bs[nb][lk + j][lr] = br0[j];
                Bs[nb][lk + j][64 + lr] = br1[j];
            }
            __syncthreads();
            buf = nb;
        }
    }

    const float4 bia0 = *reinterpret_cast<const float4*>(bias + n0 + (tx << 2));
    const float4 bia1 = *reinterpret_cast<const float4*>(bias + n0 + 64 + (tx << 2));
#pragma unroll
    for (int i = 0; i < 4; i++) {
        float* cr = C + (size_t)(m0 + (ty << 2) + i) * ldc + n0;
        float4 o0, o1;
        o0.x = acc[i][0] + bia0.x; o0.y = acc[i][1] + bia0.y;
        o0.z = acc[i][2] + bia0.z; o0.w = acc[i][3] + bia0.w;
        o1.x = acc[i][4] + bia1.x; o1.y = acc[i][5] + bia1.y;
        o1.z = acc[i][6] + bia1.z; o1.w = acc[i][7] + bia1.w;
        *reinterpret_cast<float4*>(cr + (tx << 2)) = o0;
        *reinterpret_cast<float4*>(cr + 64 + (tx << 2)) = o1;
    }
}

// ============ fc GEMM on compacted active rows (gather A, scatter C) ========
__global__ __launch_bounds__(256) void gemm_fc_kernel(
    const float* __restrict__ W, const float* __restrict__ bias,
    float* __restrict__ out)
{
    const int nact = g_nact;
    const int m0 = blockIdx.y * 64;
    if (m0 >= nact) return;

    __shared__ float As[2][16][68];
    __shared__ float Bs[2][16][136];

    const int tid = threadIdx.x;
    const int tx = tid & 15;
    const int ty = tid >> 4;
    const int n0 = blockIdx.x * 128;
    const int lr = tid >> 2;
    const int lk = (tid & 3) << 2;

    int rl = m0 + lr; if (rl > nact - 1) rl = nact - 1;
    const int vload = g_list[rl];                 // = t*64 + b = hall row
    const float* aP  = g_hall + (size_t)vload * DEC_ + lk;
    const float* bP0 = W + (size_t)(n0 + lr) * DEC_ + lk;
    const float* bP1 = W + (size_t)(n0 + 64 + lr) * DEC_ + lk;

    float acc[4][8];
#pragma unroll
    for (int i = 0; i < 4; i++)
#pragma unroll
        for (int j = 0; j < 8; j++) acc[i][j] = 0.f;

    const int nsl = DEC_ >> 4;   // 32
    float4 a  = *reinterpret_cast<const float4*>(aP);
    float4 b0 = *reinterpret_cast<const float4*>(bP0);
    float4 b1 = *reinterpret_cast<const float4*>(bP1);
    {
        float ar[4] = {a.x, a.y, a.z, a.w};
        float br0[4] = {b0.x, b0.y, b0.z, b0.w};
        float br1[4] = {b1.x, b1.y, b1.z, b1.w};
#pragma unroll
        for (int j = 0; j < 4; j++) {
            As[0][lk + j][lr] = ar[j];
            Bs[0][lk + j][lr] = br0[j];
            Bs[0][lk + j][64 + lr] = br1[j];
        }
    }
    __syncthreads();

    int buf = 0;
    for (int s = 0; s < nsl; s++) {
        if (s + 1 < nsl) {
            a  = *reinterpret_cast<const float4*>(aP  + (s + 1) * 16);
            b0 = *reinterpret_cast<const float4*>(bP0 + (s + 1) * 16);
            b1 = *reinterpret_cast<const float4*>(bP1 + (s + 1) * 16);
        }
#pragma unroll
        for (int kk = 0; kk < 16; kk++) {
            float4 av  = *reinterpret_cast<const float4*>(&As[buf][kk][ty << 2]);
            float4 bv0 = *reinterpret_cast<const float4*>(&Bs[buf][kk][tx << 2]);
            float4 bv1 = *reinterpret_cast<const float4*>(&Bs[buf][kk][64 + (tx << 2)]);
            float ar[4] = {av.x, av.y, av.z, av.w};
            float br[8] = {bv0.x, bv0.y, bv0.z, bv0.w, bv1.x, bv1.y, bv1.z, bv1.w};
#pragma unroll
            for (int i = 0; i < 4; i++)
#pragma unroll
                for (int j = 0; j < 8; j++)
                    acc[i][j] = fmaf(ar[i], br[j], acc[i][j]);
        }
        if (s + 1 < nsl) {
            int nb = buf ^ 1;
            float ar[4] = {a.x, a.y, a.z, a.w};
            float br0[4] = {b0.x, b0.y, b0.z, b0.w};
            float br1[4] = {b1.x, b1.y, b1.z, b1.w};
#pragma unroll
            for (int j = 0; j < 4; j++) {
                As[nb][lk + j][lr] = ar[j];
                Bs[nb][lk + j][lr] = br0[j];
                Bs[nb][lk + j][64 + lr] = br1[j];
            }
            __syncthreads();
            buf = nb;
        }
    }

    const float4 bia0 = *reinterpret_cast<const float4*>(bias + n0 + (tx << 2));
    const float4 bia1 = *reinterpret_cast<const float4*>(bias + n0 + 64 + (tx << 2));
#pragma unroll
    for (int i = 0; i < 4; i++) {
        const int r = m0 + (ty << 2) + i;
        if (r < nact) {
            const int v = g_list[r];
            const int b = v & 63, t = v >> 6;
            float* cr = out + ((size_t)b * T_ + t) * V_ + n0;
            float4 o0, o1;
            o0.x = acc[i][0] + bia0.x; o0.y = acc[i][1] + bia0.y;
            o0.z = acc[i][2] + bia0.z; o0.w = acc[i][3] + bia0.w;
            o1.x = acc[i][4] + bia1.x; o1.y = acc[i][5] + bia1.y;
            o1.z = acc[i][6] + bia1.z; o1.w = acc[i][7] + bia1.w;
            *reinterpret_cast<float4*>(cr + (tx << 2)) = o0;
            *reinterpret_cast<float4*>(cr + 64 + (tx << 2)) = o1;
        }
    }
}

// ============ split-K small GEMM: 64x64 tile, M=64 fixed, partials out ======
// Cp[blockIdx.y][m][n] = sum_{k in slice} A[m][k]*W[n][k]
__global__ __launch_bounds__(256) void gemm_sk_kernel(
    const float* __restrict__ A, int lda,
    const float* __restrict__ W, int ldw,
    float* __restrict__ Cp, int N, int Kslice)
{
    __shared__ float As[2][16][68];
    __shared__ float Ws[2][16][68];

    const int tid = threadIdx.x;
    const int tx = tid & 15;
    const int ty = tid >> 4;
    const int n0 = blockIdx.x * 64;
    const int k0 = blockIdx.y * Kslice;
    const int lr = tid >> 2;
    const int lk = (tid & 3) << 2;

    const float* aP = A + (size_t)lr * lda + k0 + lk;
    const float* wP = W + (size_t)(n0 + lr) * ldw + k0 + lk;

    float acc[4][4];
#pragma unroll
    for (int i = 0; i < 4; i++)
#pragma unroll
        for (int j = 0; j < 4; j++) acc[i][j] = 0.f;

    const int nsl = Kslice >> 4;
    float4 a = *reinterpret_cast<const float4*>(aP);
    float4 w = *reinterpret_cast<const float4*>(wP);
    {
        float ar[4] = {a.x, a.y, a.z, a.w};
        float wr[4] = {w.x, w.y, w.z, w.w};
#pragma unroll
        for (int j = 0; j < 4; j++) {
            As[0][lk + j][lr] = ar[j];
            Ws[0][lk + j][lr] = wr[j];
        }
    }
    __syncthreads();

    int buf = 0;
    for (int s = 0; s < nsl; s++) {
        if (s + 1 < nsl) {
            a = *reinterpret_cast<const float4*>(aP + (s + 1) * 16);
            w = *reinterpret_cast<const float4*>(wP + (s + 1) * 16);
        }
#pragma unroll
        for (int kk = 0; kk < 16; kk++) {
            float4 av = *reinterpret_cast<const float4*>(&As[buf][kk][ty << 2]);
            float4 wv = *reinterpret_cast<const float4*>(&Ws[buf][kk][tx << 2]);
            float ar[4] = {av.x, av.y, av.z, av.w};
            float wr[4] = {wv.x, wv.y, wv.z, wv.w};
#pragma unroll
            for (int i = 0; i < 4; i++)
#pragma unroll
                for (int j = 0; j < 4; j++)
                    acc[i][j] = fmaf(ar[i], wr[j], acc[i][j]);
        }
        if (s + 1 < nsl) {
            int nb = buf ^ 1;
            float ar[4] = {a.x, a.y, a.z, a.w};
            float wr[4] = {w.x, w.y, w.z, w.w};
#pragma unroll
            for (int j = 0; j < 4; j++) {
                As[nb][lk + j][lr] = ar[j];
                Ws[nb][lk + j][lr] = wr[j];
            }
            __syncthreads();
            buf = nb;
        }
    }

    float* cp = Cp + (size_t)blockIdx.y * 64 * N;
#pragma unroll
    for (int i = 0; i < 4; i++) {
        float4 o;
        o.x = acc[i][0]; o.y = acc[i][1]; o.z = acc[i][2]; o.w = acc[i][3];
        *reinterpret_cast<float4*>(cp + (size_t)((ty << 2) + i) * N + n0 + (tx << 2)) = o;
    }
}

// ============ legacy 64x64 GEMM with bias (used once for h0/c0) =============
__global__ __launch_bounds__(256) void gemm64_kernel(
    const float* __restrict__ A, int lda,
    const float* __restrict__ W, int ldw,
    const float* __restrict__ bias,
    float* __restrict__ C, int ldc, int K)
{
    __shared__ __align__(16) float As[16][64];
    __shared__ __align__(16) float Ws[16][64];

    const int tid = threadIdx.x;
    const int m0 = blockIdx.y * 64;
    const int n0 = blockIdx.x * 64;
    const int lr = tid >> 2;
    const int lk = (tid & 3) << 2;
    const int tx = tid & 15;
    const int ty = tid >> 4;

    float acc[4][4];
#pragma unroll
    for (int i = 0; i < 4; i++)
#pragma unroll
        for (int j = 0; j < 4; j++) acc[i][j] = 0.f;

    const float* aptr = A + (size_t)(m0 + lr) * lda + lk;
    const float* wptr = W + (size_t)(n0 + lr) * ldw + lk;

    for (int k0 = 0; k0 < K; k0 += 16) {
        float4 av = *reinterpret_cast<const float4*>(aptr + k0);
        float4 wv = *reinterpret_cast<const float4*>(wptr + k0);
        As[lk + 0][lr] = av.x; As[lk + 1][lr] = av.y;
        As[lk + 2][lr] = av.z; As[lk + 3][lr] = av.w;
        Ws[lk + 0][lr] = wv.x; Ws[lk + 1][lr] = wv.y;
        Ws[lk + 2][lr] = wv.z; Ws[lk + 3][lr] = wv.w;
        __syncthreads();
#pragma unroll
        for (int kk = 0; kk < 16; kk++) {
            float4 a = *reinterpret_cast<const float4*>(&As[kk][ty << 2]);
            float4 b = *reinterpret_cast<const float4*>(&Ws[kk][tx << 2]);
            float ar[4] = {a.x, a.y, a.z, a.w};
            float br[4] = {b.x, b.y, b.z, b.w};
#pragma unroll
            for (int i = 0; i < 4; i++)
#pragma unroll
                for (int j = 0; j < 4; j++)
                    acc[i][j] = fmaf(ar[i], br[j], acc[i][j]);
        }
        __syncthreads();
    }

    const int n = n0 + (tx << 2);
#pragma unroll
    for (int i = 0; i < 4; i++) {
        const int m = m0 + (ty << 2) + i;
        float4 outv;
        outv.x = acc[i][0] + bias[n + 0];
        outv.y = acc[i][1] + bias[n + 1];
        outv.z = acc[i][2] + bias[n + 2];
        outv.w = acc[i][3] + bias[n + 3];
        *reinterpret_cast<float4*>(&C[(size_t)m * ldc + n]) = outv;
    }
}

// ---------------- one-time prep kernels ----------------
__global__ void prep_weights_kernel(
    const float* __restrict__ Wdec, const float* __restrict__ bdec,
    const float* __restrict__ Wbeta, const float* __restrict__ bbeta,
    const float* __restrict__ Wih, const float* __restrict__ Whh,
    const float* __restrict__ bih, const float* __restrict__ bhh,
    const float* __restrict__ Winith, const float* __restrict__ binith,
    const float* __restrict__ Winitc, const float* __restrict__ binitc)
{
    const int stride = gridDim.x * blockDim.x;
    const int i0 = blockIdx.x * blockDim.x + threadIdx.x;
    for (int i = i0; i < 512 * 512; i += stride) {
        g_Wab[i] = Wdec[i];
        g_Wab[512 * 512 + i] = Wbeta[i];
        g_Winit[i] = Winith[i];
        g_Winit[512 * 512 + i] = Winitc[i];
    }
    for (int i = i0; i < 512; i += stride) {
        g_bab[i] = bdec[i];       g_bab[512 + i] = bbeta[i];
        g_binit[i] = binith[i];   g_binit[512 + i] = binitc[i];
    }
    for (int i = i0; i < 2048 * 1280; i += stride) {
        int nrow = i / 1280, k = i - nrow * 1280;
        g_Wlstm[i] = (k < 768) ? Wih[nrow * 768 + k] : Whh[nrow * 512 + (k - 768)];
    }
    for (int i = i0; i < 2048; i += stride) g_blstm[i] = bih[i] + bhh[i];
}

__global__ void build_list_kernel(const int* __restrict__ lens)
{
    __shared__ int offs[64];
    const int b = threadIdx.x;
    if (b == 0) {
        int o = 0;
        for (int i = 0; i < B_; i++) { offs[i] = o; o += lens[i] - 1; }
        g_nact = o;
    }
    __syncthreads();
    if (b < B_) {
        const int o = offs[b];
        const int n = lens[b] - 1;
        for (int t = 0; t < n; t++) g_list[o + t] = (t << 6) | b;
    }
}

__global__ void zerofill_kernel(const int* __restrict__ lens, float* __restrict__ out)
{
    const int b = blockIdx.x / T_;
    const int t = blockIdx.x % T_;
    if (t < lens[b] - 1) return;
    float4 z; z.x = z.y = z.z = z.w = 0.f;
    float4* o = reinterpret_cast<float4*>(out + ((size_t)b * T_ + t) * V_);
    for (int i = threadIdx.x; i < V_ / 4; i += blockDim.x) o[i] = z;
}

// encoder_out [b][c][p] -> g_encflat [b][p][c]
__global__ void transpose_enc_kernel(const float* __restrict__ EO)
{
    __shared__ float tile[32][33];
    const int b = blockIdx.z;
    const int c0 = blockIdx.y * 32;
    const int p0 = blockIdx.x * 32;
    const int tx = threadIdx.x, ty = threadIdx.y;
#pragma unroll
    for (int j = 0; j < 32; j += 8)
        tile[ty + j][tx] = EO[((size_t)b * ENC_ + (c0 + ty + j)) * P_ + p0 + tx];
    __syncthreads();
#pragma unroll
    for (int j = 0; j < 32; j += 8)
        g_encflat[((size_t)b * P_ + (p0 + ty + j)) * ENC_ + c0 + tx] = tile[tx][ty + j];
}

__global__ void meanenc_kernel(const float* __restrict__ EO)
{
    const int wg = (blockIdx.x * blockDim.x + threadIdx.x) >> 5;
    const int lane = threadIdx.x & 31;
    if (wg >= B_ * ENC_) return;
    const float* row = EO + (size_t)wg * P_;
    float s = 0.f;
    for (int p = lane; p < P_; p += 32) s += row[p];
#pragma unroll
    for (int o = 16; o; o >>= 1) s += __shfl_xor_sync(0xffffffffu, s, o);
    if (!lane) g_meanenc[wg] = s * (1.0f / P_);
}

// ---------------- per-step fused attention kernel ----------------
// One block per batch row b. Reduces att2/beta split-K partials, computes
// energies (relu(att1+att2)·w + b), softmax, gated awe, assembles xinh.
__global__ __launch_bounds__(256) void attention_kernel(
    const float* __restrict__ EO, const float* __restrict__ emb,
    const int* __restrict__ caps, const float* __restrict__ wfull,
    const float* __restrict__ bfull, int t)
{
    __shared__ float attb[1024];   // att2 logits | beta logits (bias included)
    __shared__ float ws[512];
    __shared__ float es[256];
    __shared__ float red[8];
    __shared__ float sval;

    const int b = blockIdx.x;
    const int tid = threadIdx.x, lane = tid & 31, warp = tid >> 5;

    for (int a = tid; a < 1024; a += 256) {
        float s = g_bab[a];
#pragma unroll
        for (int p = 0; p < AB_KSPLIT; p++)
            s += g_abp[(size_t)p * (B_ * 1024) + b * 1024 + a];
        attb[a] = s;
    }
    ws[tid] = wfull[tid];
    ws[tid + 256] = wfull[tid + 256];
    __syncthreads();

    const float bf = bfull[0];
    for (int p = warp; p < P_; p += 8) {
        const float* arow = g_att1 + ((size_t)b * P_ + p) * ATT_;
        float s = 0.f;
        for (int a = lane; a < ATT_; a += 32) {
            float v = arow[a] + attb[a];
            v = fmaxf(v, 0.f);
            s = fmaf(v, ws[a], s);
        }
#pragma unroll
        for (int o = 16; o; o >>= 1) s += __shfl_xor_sync(0xffffffffu, s, o);
        if (!lane) es[p] = s + bf;
    }
    __syncthreads();

    float v = es[tid];
    float mx = v;
#pragma unroll
    for (int o = 16; o; o >>= 1) mx = fmaxf(mx, __shfl_xor_sync(0xffffffffu, mx, o));
    if (!lane) red[warp] = mx;
    __syncthreads();
    if (tid == 0) {
        float mm = red[0];
#pragma unroll
        for (int i = 1; i < 8; i++) mm = fmaxf(mm, red[i]);
        sval = mm;
    }
    __syncthreads();
    float ex = __expf(v - sval);
    float s2 = ex;
#pragma unroll
    for (int o = 16; o; o >>= 1) s2 += __shfl_xor_sync(0xffffffffu, s2, o);
    if (!lane) red[warp] = s2;
    __syncthreads();
    if (tid == 0) {
        float ss = 0.f;
#pragma unroll
        for (int i = 0; i < 8; i++) ss += red[i];
        sval = ss;
    }
    __syncthreads();
    es[tid] = ex / sval;   // alpha
    __syncthreads();

    for (int c = warp; c < ENC_; c += 8) {
        const float* eop = EO + ((size_t)b * ENC_ + c) * P_;
        float s = 0.f;
        for (int p = lane; p < P_; p += 32) s = fmaf(es[p], eop[p], s);
#pragma unroll
        for (int o = 16; o; o >>= 1) s += __shfl_xor_sync(0xffffffffu, s, o);
        if (!lane) {
            float gl = attb[512 + c];
            float gate = 1.f / (1.f + __expf(-gl));
            g_xinh[b * 1280 + 256 + c] = gate * s;
        }
    }

    const int tok = caps[b * L_ + t];
    g_xinh[b * 1280 + tid] = emb[(size_t)tok * EMB_ + tid];
    g_xinh[b * 1280 + 768 + tid]       = g_state[b * 1024 + tid];
    g_xinh[b * 1280 + 768 + 256 + tid] = g_state[b * 1024 + 256 + tid];
}

// ---------------- LSTM cell (reduces gate split-K partials) ----------------
__global__ void lstm_cell_kernel(int t)
{
    const int b = blockIdx.x, d = threadIdx.x;
    float gi = g_blstm[d];
    float gf = g_blstm[512 + d];
    float gg = g_blstm[1024 + d];
    float go = g_blstm[1536 + d];
#pragma unroll
    for (int s = 0; s < G_KSPLIT; s++) {
        const float* base = g_gp + (size_t)s * (B_ * 2048) + b * 2048;
        gi += base[d];
        gf += base[512 + d];
        gg += base[1024 + d];
        go += base[1536 + d];
    }
    const float c = g_state[b * 1024 + 512 + d];
    const float si = 1.f / (1.f + __expf(-gi));
    const float sf = 1.f / (1.f + __expf(-gf));
    const float so = 1.f / (1.f + __expf(-go));
    const float c2 = sf * c + si * tanhf(gg);
    const float h2 = so * tanhf(c2);
    g_state[b * 1024 + d] = h2;
    g_state[b * 1024 + 512 + d] = c2;
    g_hall[((size_t)t * B_ + b) * DEC_ + d] = h2;
}

// ---------------- launch ----------------
extern "C" void kernel_launch(void* const* d_in, const int* in_sizes, int n_in,
                              void* d_out, int out_size)
{
    const float* EO        = (const float*)d_in[0];
    const int*   caps      = (const int*)  d_in[1];
    const int*   lens      = (const int*)  d_in[2];
    const float* W_enc_att = (const float*)d_in[3];
    const float* b_enc_att = (const float*)d_in[4];
    const float* W_dec_att = (const float*)d_in[5];
    const float* b_dec_att = (const float*)d_in[6];
    const float* w_full    = (const float*)d_in[7];
    const float* b_full    = (const float*)d_in[8];
    const float* emb       = (const float*)d_in[9];
    const float* W_ih      = (const float*)d_in[10];
    const float* W_hh      = (const float*)d_in[11];
    const float* b_ih      = (const float*)d_in[12];
    const float* b_hh      = (const float*)d_in[13];
    const float* W_init_h  = (const float*)d_in[14];
    const float* b_init_h  = (const float*)d_in[15];
    const float* W_init_c  = (const float*)d_in[16];
    const float* b_init_c  = (const float*)d_in[17];
    const float* W_beta    = (const float*)d_in[18];
    const float* b_beta    = (const float*)d_in[19];
    const float* W_fc      = (const float*)d_in[20];
    const float* b_fc      = (const float*)d_in[21];
    float* out = (float*)d_out;

    float *state, *meanenc, *encflat, *att1, *Wab, *Winit, *binit;
    float *Wlstm, *xinh, *abp, *gp;
    cudaGetSymbolAddress((void**)&state,   g_state);
    cudaGetSymbolAddress((void**)&meanenc, g_meanenc);
    cudaGetSymbolAddress((void**)&encflat, g_encflat);
    cudaGetSymbolAddress((void**)&att1,    g_att1);
    cudaGetSymbolAddress((void**)&Wab,     g_Wab);
    cudaGetSymbolAddress((void**)&Winit,   g_Winit);
    cudaGetSymbolAddress((void**)&binit,   g_binit);
    cudaGetSymbolAddress((void**)&Wlstm,   g_Wlstm);
    cudaGetSymbolAddress((void**)&xinh,    g_xinh);
    cudaGetSymbolAddress((void**)&abp,     g_abp);
    cudaGetSymbolAddress((void**)&gp,      g_gp);

    // ---- one-time prep ----
    prep_weights_kernel<<<512, 256>>>(W_dec_att, b_dec_att, W_beta, b_beta,
                                      W_ih, W_hh, b_ih, b_hh,
                                      W_init_h, b_init_h, W_init_c, b_init_c);
    build_list_kernel<<<1, 64>>>(lens);
    zerofill_kernel<<<B_ * T_, 256>>>(lens, out);
    transpose_enc_kernel<<<dim3(8, 16, 64), dim3(32, 8)>>>(EO);
    meanenc_kernel<<<4096, 256>>>(EO);
    gemm64_kernel<<<dim3(16, 1), 256>>>(meanenc, 512, Winit, 512, binit,
                                        state, 1024, 512);
    // att1 = encflat @ W_enc_att^T + b : [16384 x 512]
    gemm_big_kernel<<<dim3(4, 256), 256>>>(encflat, 512, W_enc_att, 512,
                                           b_enc_att, att1, 512, 512);

    // ---- 31 sequential decode steps ----
    for (int t = 0; t < T_; t++) {
        // att2|beta partials: h @ [W_dec_att;W_beta]^T   (K=512, 8 splits)
        gemm_sk_kernel<<<dim3(16, AB_KSPLIT), 256>>>(state, 1024, Wab, 512,
                                                     abp, 1024, 512 / AB_KSPLIT);
        attention_kernel<<<64, 256>>>(EO, emb, caps, w_full, b_full, t);
        // gates partials: [xin|h] @ [W_ih|W_hh]^T        (K=1280, 10 splits)
        gemm_sk_kernel<<<dim3(32, G_KSPLIT), 256>>>(xinh, 1280, Wlstm, 1280,
                                                    gp, 2048, 1280 / G_KSPLIT);
        lstm_cell_kernel<<<64, 512>>>(t);
    }

    // ---- all predictions in one big GEMM over active rows ----
    gemm_fc_kernel<<<dim3(125, 31), 256>>>(W_fc, b_fc, out);
}

// round 4
// speedup vs baseline: 3.3571x; 1.4612x over previous
#include <cuda_runtime.h>

#define B_   64
#define L_   32
#define T_   31
#define V_   16000
#define ENC_ 512
#define DEC_ 512
#define ATT_ 512
#define EMB_ 256
#define P_   256

#define NB_    128   // persistent kernel blocks (<= 148 SMs -> all co-resident)
#define GKS_   4     // gates split-K factor inside persistent kernel

// ---------------- device scratch ----------------
__device__ float g_state[B_ * 1024];            // [h(512) | c(512)]
__device__ float g_meanenc[B_ * ENC_];
__device__ float g_att1[B_ * P_ * ATT_];
__device__ float g_Wab[1024 * 512];             // [W_dec_att ; W_beta]
__device__ float g_bab[1024];
__device__ float g_Winit[1024 * 512];
__device__ float g_binit[1024];
__device__ float g_Wlstm[2048 * 1280];          // [W_ih | W_hh]
__device__ float g_blstm[2048];
__device__ float g_ab[B_ * 1024];
__device__ float g_xinh[B_ * 1280];
__device__ float g_gp[GKS_ * B_ * 2048];
__device__ float g_hall[T_ * B_ * DEC_];
__device__ int   g_list[T_ * B_];
__device__ int   g_nact;
__device__ unsigned g_bar_count = 0;
__device__ unsigned g_bar_gen   = 0;

__device__ __forceinline__ float4 ldcg4(const float* p) {
    return __ldcg(reinterpret_cast<const float4*>(p));
}

// ---------------- software grid barrier (all NB_ blocks co-resident) -------
__device__ __forceinline__ void grid_bar() {
    __syncthreads();
    if (threadIdx.x == 0) {
        __threadfence();
        unsigned gen = *((volatile unsigned*)&g_bar_gen);
        unsigned t = atomicAdd(&g_bar_count, 1u);
        if (t == NB_ - 1) {
            g_bar_count = 0;
            __threadfence();
            *((volatile unsigned*)&g_bar_gen) = gen + 1;
        } else {
            while (*((volatile unsigned*)&g_bar_gen) == gen) __nanosleep(64);
        }
    }
    __syncthreads();
}

// ================= persistent decode-loop kernel =================
__global__ __launch_bounds__(256, 1) void step_kernel(
    const float* __restrict__ EO, const float* __restrict__ emb,
    const int* __restrict__ caps, const float* __restrict__ wfull,
    const float* __restrict__ bfull)
{
    __shared__ __align__(16) float pool[4360];
    const int tid = threadIdx.x;
    const int lane = tid & 31, warp = tid >> 5;

    for (int t = 0; t < T_; t++) {
        // ---- Phase A: ab[64x1024] = h @ Wab^T + bab ----
        {
            float* Ws = pool;                   // 8 rows x 516 (padded)
            const int n0 = blockIdx.x * 8;
            for (int i = tid; i < 8 * 512; i += 256) {
                const int r = i >> 9, c = i & 511;
                Ws[r * 516 + c] = g_Wab[(size_t)(n0 + r) * 512 + c];
            }
            __syncthreads();
            const int b = tid >> 2;
            const int nl0 = (tid & 3) << 1;
            const float* hb = g_state + b * 1024;
            const float* w0p = Ws + nl0 * 516;
            const float* w1p = Ws + (nl0 + 1) * 516;
            float4 s0 = {0.f,0.f,0.f,0.f}, s1 = {0.f,0.f,0.f,0.f};
#pragma unroll 4
            for (int k = 0; k < 512; k += 4) {
                float4 hv = ldcg4(hb + k);
                float4 w0 = *reinterpret_cast<const float4*>(w0p + k);
                float4 w1 = *reinterpret_cast<const float4*>(w1p + k);
                s0.x = fmaf(hv.x, w0.x, s0.x); s0.y = fmaf(hv.y, w0.y, s0.y);
                s0.z = fmaf(hv.z, w0.z, s0.z); s0.w = fmaf(hv.w, w0.w, s0.w);
                s1.x = fmaf(hv.x, w1.x, s1.x); s1.y = fmaf(hv.y, w1.y, s1.y);
                s1.z = fmaf(hv.z, w1.z, s1.z); s1.w = fmaf(hv.w, w1.w, s1.w);
            }
            g_ab[b * 1024 + n0 + nl0]     = s0.x + s0.y + s0.z + s0.w + g_bab[n0 + nl0];
            g_ab[b * 1024 + n0 + nl0 + 1] = s1.x + s1.y + s1.z + s1.w + g_bab[n0 + nl0 + 1];
        }
        grid_bar();

        // ---- Phase B: attention + softmax + gated awe + xinh assembly ----
        if (blockIdx.x < 64) {
            float* attb = pool;            // 1024
            float* ws   = pool + 1024;     // 512
            float* es   = pool + 1536;     // 256
            float* red  = pool + 1792;     // 8
            float* sv   = pool + 1800;     // 1
            const int b = blockIdx.x;

            for (int a = tid; a < 1024; a += 256) attb[a] = __ldcg(&g_ab[b * 1024 + a]);
            ws[tid] = wfull[tid];
            ws[tid + 256] = wfull[tid + 256];
            __syncthreads();

            const float bf = bfull[0];
            for (int p = warp; p < P_; p += 8) {
                const float* arow = g_att1 + ((size_t)b * P_ + p) * ATT_;
                float s = 0.f;
                for (int a = lane; a < ATT_; a += 32) {
                    float v = arow[a] + attb[a];
                    v = fmaxf(v, 0.f);
                    s = fmaf(v, ws[a], s);
                }
#pragma unroll
                for (int o = 16; o; o >>= 1) s += __shfl_xor_sync(0xffffffffu, s, o);
                if (!lane) es[p] = s + bf;
            }
            __syncthreads();

            float v = es[tid];
            float mx = v;
#pragma unroll
            for (int o = 16; o; o >>= 1) mx = fmaxf(mx, __shfl_xor_sync(0xffffffffu, mx, o));
            if (!lane) red[warp] = mx;
            __syncthreads();
            if (tid == 0) {
                float mm = red[0];
#pragma unroll
                for (int i = 1; i < 8; i++) mm = fmaxf(mm, red[i]);
                sv[0] = mm;
            }
            __syncthreads();
            float ex = __expf(v - sv[0]);
            float s2 = ex;
#pragma unroll
            for (int o = 16; o; o >>= 1) s2 += __shfl_xor_sync(0xffffffffu, s2, o);
            if (!lane) red[warp] = s2;
            __syncthreads();
            if (tid == 0) {
                float ss = 0.f;
#pragma unroll
                for (int i = 0; i < 8; i++) ss += red[i];
                sv[0] = ss;
            }
            __syncthreads();
            es[tid] = ex / sv[0];
            __syncthreads();

            for (int c = warp; c < ENC_; c += 8) {
                const float* eop = EO + ((size_t)b * ENC_ + c) * P_;
                float s = 0.f;
                for (int p = lane; p < P_; p += 32) s = fmaf(es[p], eop[p], s);
#pragma unroll
                for (int o = 16; o; o >>= 1) s += __shfl_xor_sync(0xffffffffu, s, o);
                if (!lane) {
                    float gate = 1.f / (1.f + __expf(-attb[512 + c]));
                    g_xinh[b * 1280 + 256 + c] = gate * s;
                }
            }
            const int tok = caps[b * L_ + t];
            g_xinh[b * 1280 + tid] = emb[(size_t)tok * EMB_ + tid];
            g_xinh[b * 1280 + 768 + tid]       = __ldcg(&g_state[b * 1024 + tid]);
            g_xinh[b * 1280 + 768 + 256 + tid] = __ldcg(&g_state[b * 1024 + 256 + tid]);
        }
        grid_bar();

        // ---- Phase C: gates split-K GEMM (64x2048, K=1280 in 4 slices) ----
        {
            float (*As2)[16][68] = reinterpret_cast<float(*)[16][68]>(pool);
            float (*Ws2)[16][68] = reinterpret_cast<float(*)[16][68]>(pool + 2176);
            const int jn = blockIdx.x & 31, jk = blockIdx.x >> 5;
            const int n0 = jn * 64, k0 = jk * 320;
            const int lr = tid >> 2, lk = (tid & 3) << 2;
            const int tx = tid & 15, ty = tid >> 4;
            const float* aP = g_xinh + lr * 1280 + k0 + lk;
            const float* wP = g_Wlstm + (size_t)(n0 + lr) * 1280 + k0 + lk;

            float acc[4][4];
#pragma unroll
            for (int i = 0; i < 4; i++)
#pragma unroll
                for (int j = 0; j < 4; j++) acc[i][j] = 0.f;

            float4 a = ldcg4(aP);
            float4 w = *reinterpret_cast<const float4*>(wP);
            {
                float ar[4] = {a.x, a.y, a.z, a.w};
                float wr[4] = {w.x, w.y, w.z, w.w};
#pragma unroll
                for (int j = 0; j < 4; j++) {
                    As2[0][lk + j][lr] = ar[j];
                    Ws2[0][lk + j][lr] = wr[j];
                }
            }
            __syncthreads();
            int buf = 0;
            for (int s = 0; s < 20; s++) {
                if (s + 1 < 20) {
                    a = ldcg4(aP + (s + 1) * 16);
                    w = *reinterpret_cast<const float4*>(wP + (s + 1) * 16);
                }
#pragma unroll
                for (int kk = 0; kk < 16; kk++) {
                    float4 av = *reinterpret_cast<const float4*>(&As2[buf][kk][ty << 2]);
                    float4 wv = *reinterpret_cast<const float4*>(&Ws2[buf][kk][tx << 2]);
                    float ar[4] = {av.x, av.y, av.z, av.w};
                    float wr[4] = {wv.x, wv.y, wv.z, wv.w};
#pragma unroll
                    for (int i = 0; i < 4; i++)
#pragma unroll
                        for (int j = 0; j < 4; j++)
                            acc[i][j] = fmaf(ar[i], wr[j], acc[i][j]);
                }
                if (s + 1 < 20) {
                    int nb = buf ^ 1;
                    float ar[4] = {a.x, a.y, a.z, a.w};
                    float wr[4] = {w.x, w.y, w.z, w.w};
#pragma unroll
                    for (int j = 0; j < 4; j++) {
                        As2[nb][lk + j][lr] = ar[j];
                        Ws2[nb][lk + j][lr] = wr[j];
                    }
                    __syncthreads();
                    buf = nb;
                }
            }
            float* cp = g_gp + (size_t)jk * (B_ * 2048);
#pragma unroll
            for (int i = 0; i < 4; i++) {
                float4 o;
                o.x = acc[i][0]; o.y = acc[i][1]; o.z = acc[i][2]; o.w = acc[i][3];
                *reinterpret_cast<float4*>(cp + (size_t)((ty << 2) + i) * 2048 + n0 + (tx << 2)) = o;
            }
        }
        grid_bar();

        // ---- Phase D: LSTM cell (reduce 4 partials) ----
        if (blockIdx.x < 64) {
            const int b = blockIdx.x;
            for (int dd = tid; dd < 512; dd += 256) {
                float gi = g_blstm[dd];
                float gf = g_blstm[512 + dd];
                float gg = g_blstm[1024 + dd];
                float go = g_blstm[1536 + dd];
#pragma unroll
                for (int s = 0; s < GKS_; s++) {
                    const float* base = g_gp + (size_t)s * (B_ * 2048) + b * 2048;
                    gi += __ldcg(base + dd);
                    gf += __ldcg(base + 512 + dd);
                    gg += __ldcg(base + 1024 + dd);
                    go += __ldcg(base + 1536 + dd);
                }
                const float c = __ldcg(&g_state[b * 1024 + 512 + dd]);
                const float si = 1.f / (1.f + __expf(-gi));
                const float sf = 1.f / (1.f + __expf(-gf));
                const float so = 1.f / (1.f + __expf(-go));
                const float c2 = sf * c + si * tanhf(gg);
                const float h2 = so * tanhf(c2);
                g_state[b * 1024 + dd] = h2;
                g_state[b * 1024 + 512 + dd] = c2;
                g_hall[((size_t)t * B_ + b) * DEC_ + dd] = h2;
            }
        }
        grid_bar();
    }
}

// ================= 128x128 / 8x8 double-buffered SGEMMs =================
// att1: C[m][n] = sum_k EO[b][k][p] * W[n][k] + bias[n], m = b*256 + p
__global__ __launch_bounds__(256) void att1_gemm_kernel(
    const float* __restrict__ EO, const float* __restrict__ W,
    const float* __restrict__ bias)
{
    __shared__ __align__(16) float As[2][16][136];
    __shared__ __align__(16) float Bs[2][16][136];
    const int tid = threadIdx.x;
    const int tx = tid & 15, ty = tid >> 4;
    const int n0 = blockIdx.x * 128;
    const int m0 = blockIdx.y * 128;
    const int b  = blockIdx.y >> 1;
    const int p0 = (blockIdx.y & 1) * 128;
    const int ia = tid * 2;

    float acc[8][8];
#pragma unroll
    for (int i = 0; i < 8; i++)
#pragma unroll
        for (int j = 0; j < 8; j++) acc[i][j] = 0.f;

    float4 va[2], vb[2];
#pragma unroll
    for (int j = 0; j < 2; j++) {
        const int i = ia + j;
        const int k = i >> 5, p = (i & 31) << 2;
        va[j] = *reinterpret_cast<const float4*>(
            EO + ((size_t)b * 512 + k) * 256 + p0 + p);
        const int nr = i >> 2, kc = (i & 3) << 2;
        vb[j] = *reinterpret_cast<const float4*>(W + (size_t)(n0 + nr) * 512 + kc);
    }
#pragma unroll
    for (int j = 0; j < 2; j++) {
        const int i = ia + j;
        const int k = i >> 5, p = (i & 31) << 2;
        *reinterpret_cast<float4*>(&As[0][k][p]) = va[j];
        const int nr = i >> 2, kc = (i & 3) << 2;
        Bs[0][kc + 0][nr] = vb[j].x; Bs[0][kc + 1][nr] = vb[j].y;
        Bs[0][kc + 2][nr] = vb[j].z; Bs[0][kc + 3][nr] = vb[j].w;
    }
    __syncthreads();

    int buf = 0;
    for (int s = 0; s < 32; s++) {
        const int kn = (s + 1) * 16;
        if (s + 1 < 32) {
#pragma unroll
            for (int j = 0; j < 2; j++) {
                const int i = ia + j;
                const int k = i >> 5, p = (i & 31) << 2;
                va[j] = *reinterpret_cast<const float4*>(
                    EO + ((size_t)b * 512 + kn + k) * 256 + p0 + p);
                const int nr = i >> 2, kc = (i & 3) << 2;
                vb[j] = *reinterpret_cast<const float4*>(
                    W + (size_t)(n0 + nr) * 512 + kn + kc);
            }
        }
#pragma unroll
        for (int kk = 0; kk < 16; kk++) {
            float4 a0 = *reinterpret_cast<const float4*>(&As[buf][kk][ty << 3]);
            float4 a1 = *reinterpret_cast<const float4*>(&As[buf][kk][(ty << 3) + 4]);
            float4 b0 = *reinterpret_cast<const float4*>(&Bs[buf][kk][tx << 3]);
            float4 b1 = *reinterpret_cast<const float4*>(&Bs[buf][kk][(tx << 3) + 4]);
            float ar[8] = {a0.x, a0.y, a0.z, a0.w, a1.x, a1.y, a1.z, a1.w};
            float br[8] = {b0.x, b0.y, b0.z, b0.w, b1.x, b1.y, b1.z, b1.w};
#pragma unroll
            for (int i = 0; i < 8; i++)
#pragma unroll
                for (int j = 0; j < 8; j++)
                    acc[i][j] = fmaf(ar[i], br[j], acc[i][j]);
        }
        if (s + 1 < 32) {
            const int nb = buf ^ 1;
#pragma unroll
            for (int j = 0; j < 2; j++) {
                const int i = ia + j;
                const int k = i >> 5, p = (i & 31) << 2;
                *reinterpret_cast<float4*>(&As[nb][k][p]) = va[j];
                const int nr = i >> 2, kc = (i & 3) << 2;
                Bs[nb][kc + 0][nr] = vb[j].x; Bs[nb][kc + 1][nr] = vb[j].y;
                Bs[nb][kc + 2][nr] = vb[j].z; Bs[nb][kc + 3][nr] = vb[j].w;
            }
            __syncthreads();
            buf = nb;
        }
    }

    float bi[8];
#pragma unroll
    for (int j = 0; j < 8; j++) bi[j] = bias[n0 + (tx << 3) + j];
#pragma unroll
    for (int i = 0; i < 8; i++) {
        float* cr = g_att1 + (size_t)(m0 + (ty << 3) + i) * 512 + n0 + (tx << 3);
        float4 o0, o1;
        o0.x = acc[i][0] + bi[0]; o0.y = acc[i][1] + bi[1];
        o0.z = acc[i][2] + bi[2]; o0.w = acc[i][3] + bi[3];
        o1.x = acc[i][4] + bi[4]; o1.y = acc[i][5] + bi[5];
        o1.z = acc[i][6] + bi[6]; o1.w = acc[i][7] + bi[7];
        *reinterpret_cast<float4*>(cr) = o0;
        *reinterpret_cast<float4*>(cr + 4) = o1;
    }
}

// fc: active rows gathered via g_list; out[b][t][:] = hall_row @ W_fc^T + b_fc
__global__ __launch_bounds__(256) void fc_gemm_kernel(
    const float* __restrict__ W, const float* __restrict__ bias,
    float* __restrict__ out)
{
    const int nact = g_nact;
    const int m0 = blockIdx.y * 128;
    if (m0 >= nact) return;

    __shared__ __align__(16) float As[2][16][136];
    __shared__ __align__(16) float Bs[2][16][136];
    const int tid = threadIdx.x;
    const int tx = tid & 15, ty = tid >> 4;
    const int n0 = blockIdx.x * 128;
    const int ia = tid * 2;

    // per-thread gather row pointers (2 loads/slice)
    const float* aRow[2];
#pragma unroll
    for (int j = 0; j < 2; j++) {
        const int i = ia + j;
        int r = m0 + (i >> 2);
        if (r > nact - 1) r = nact - 1;
        aRow[j] = g_hall + (size_t)g_list[r] * DEC_ + ((i & 3) << 2);
    }

    float acc[8][8];
#pragma unroll
    for (int i = 0; i < 8; i++)
#pragma unroll
        for (int j = 0; j < 8; j++) acc[i][j] = 0.f;

    float4 va[2], vb[2];
#pragma unroll
    for (int j = 0; j < 2; j++) {
        const int i = ia + j;
        va[j] = *reinterpret_cast<const float4*>(aRow[j]);
        const int nr = i >> 2, kc = (i & 3) << 2;
        vb[j] = *reinterpret_cast<const float4*>(W + (size_t)(n0 + nr) * 512 + kc);
    }
#pragma unroll
    for (int j = 0; j < 2; j++) {
        const int i = ia + j;
        const int mr = i >> 2, kc = (i & 3) << 2;
        As[0][kc + 0][mr] = va[j].x; As[0][kc + 1][mr] = va[j].y;
        As[0][kc + 2][mr] = va[j].z; As[0][kc + 3][mr] = va[j].w;
        Bs[0][kc + 0][mr] = vb[j].x; Bs[0][kc + 1][mr] = vb[j].y;
        Bs[0][kc + 2][mr] = vb[j].z; Bs[0][kc + 3][mr] = vb[j].w;
    }
    __syncthreads();

    int buf = 0;
    for (int s = 0; s < 32; s++) {
        const int kn = (s + 1) * 16;
        if (s + 1 < 32) {
#pragma unroll
            for (int j = 0; j < 2; j++) {
                const int i = ia + j;
                va[j] = *reinterpret_cast<const float4*>(aRow[j] + kn);
                const int nr = i >> 2, kc = (i & 3) << 2;
                vb[j] = *reinterpret_cast<const float4*>(
                    W + (size_t)(n0 + nr) * 512 + kn + kc);
            }
        }
#pragma unroll
        for (int kk = 0; kk < 16; kk++) {
            float4 a0 = *reinterpret_cast<const float4*>(&As[buf][kk][ty << 3]);
            float4 a1 = *reinterpret_cast<const float4*>(&As[buf][kk][(ty << 3) + 4]);
            float4 b0 = *reinterpret_cast<const float4*>(&Bs[buf][kk][tx << 3]);
            float4 b1 = *reinterpret_cast<const float4*>(&Bs[buf][kk][(tx << 3) + 4]);
            float ar[8] = {a0.x, a0.y, a0.z, a0.w, a1.x, a1.y, a1.z, a1.w};
            float br[8] = {b0.x, b0.y, b0.z, b0.w, b1.x, b1.y, b1.z, b1.w};
#pragma unroll
            for (int i = 0; i < 8; i++)
#pragma unroll
                for (int j = 0; j < 8; j++)
                    acc[i][j] = fmaf(ar[i], br[j], acc[i][j]);
        }
        if (s + 1 < 32) {
            const int nb = buf ^ 1;
#pragma unroll
            for (int j = 0; j < 2; j++) {
                const int i = ia + j;
                const int mr = i >> 2, kc = (i & 3) << 2;
                As[nb][kc + 0][mr] = va[j].x; As[nb][kc + 1][mr] = va[j].y;
                As[nb][kc + 2][mr] = va[j].z; As[nb][kc + 3][mr] = va[j].w;
                Bs[nb][kc + 0][mr] = vb[j].x; Bs[nb][kc + 1][mr] = vb[j].y;
                Bs[nb][kc + 2][mr] = vb[j].z; Bs[nb][kc + 3][mr] = vb[j].w;
            }
            __syncthreads();
            buf = nb;
        }
    }

    float bi[8];
#pragma unroll
    for (int j = 0; j < 8; j++) bi[j] = bias[n0 + (tx << 3) + j];
#pragma unroll
    for (int i = 0; i < 8; i++) {
        const int r = m0 + (ty << 3) + i;
        if (r < nact) {
            const int v = g_list[r];
            const int b = v & 63, t = v >> 6;
            float* cr = out + ((size_t)b * T_ + t) * V_ + n0 + (tx << 3);
            float4 o0, o1;
            o0.x = acc[i][0] + bi[0]; o0.y = acc[i][1] + bi[1];
            o0.z = acc[i][2] + bi[2]; o0.w = acc[i][3] + bi[3];
            o1.x = acc[i][4] + bi[4]; o1.y = acc[i][5] + bi[5];
            o1.z = acc[i][6] + bi[6]; o1.w = acc[i][7] + bi[7];
            *reinterpret_cast<float4*>(cr) = o0;
            *reinterpret_cast<float4*>(cr + 4) = o1;
        }
    }
}

// ============ 64x64 GEMM with bias (h0/c0 init only) =============
__global__ __launch_bounds__(256) void gemm64_kernel(
    const float* __restrict__ A, int lda,
    const float* __restrict__ W, int ldw,
    const float* __restrict__ bias,
    float* __restrict__ C, int ldc, int K)
{
    __shared__ __align__(16) float As[16][64];
    __shared__ __align__(16) float Ws[16][64];
    const int tid = threadIdx.x;
    const int m0 = blockIdx.y * 64;
    const int n0 = blockIdx.x * 64;
    const int lr = tid >> 2;
    const int lk = (tid & 3) << 2;
    const int tx = tid & 15;
    const int ty = tid >> 4;

    float acc[4][4];
#pragma unroll
    for (int i = 0; i < 4; i++)
#pragma unroll
        for (int j = 0; j < 4; j++) acc[i][j] = 0.f;

    const float* aptr = A + (size_t)(m0 + lr) * lda + lk;
    const float* wptr = W + (size_t)(n0 + lr) * ldw + lk;

    for (int k0 = 0; k0 < K; k0 += 16) {
        float4 av = *reinterpret_cast<const float4*>(aptr + k0);
        float4 wv = *reinterpret_cast<const float4*>(wptr + k0);
        As[lk + 0][lr] = av.x; As[lk + 1][lr] = av.y;
        As[lk + 2][lr] = av.z; As[lk + 3][lr] = av.w;
        Ws[lk + 0][lr] = wv.x; Ws[lk + 1][lr] = wv.y;
        Ws[lk + 2][lr] = wv.z; Ws[lk + 3][lr] = wv.w;
        __syncthreads();
#pragma unroll
        for (int kk = 0; kk < 16; kk++) {
            float4 a = *reinterpret_cast<const float4*>(&As[kk][ty << 2]);
            float4 b = *reinterpret_cast<const float4*>(&Ws[kk][tx << 2]);
            float ar[4] = {a.x, a.y, a.z, a.w};
            float br[4] = {b.x, b.y, b.z, b.w};
#pragma unroll
            for (int i = 0; i < 4; i++)
#pragma unroll
                for (int j = 0; j < 4; j++)
                    acc[i][j] = fmaf(ar[i], br[j], acc[i][j]);
        }
        __syncthreads();
    }
    const int n = n0 + (tx << 2);
#pragma unroll
    for (int i = 0; i < 4; i++) {
        const int m = m0 + (ty << 2) + i;
        float4 outv;
        outv.x = acc[i][0] + bias[n + 0];
        outv.y = acc[i][1] + bias[n + 1];
        outv.z = acc[i][2] + bias[n + 2];
        outv.w = acc[i][3] + bias[n + 3];
        *reinterpret_cast<float4*>(&C[(size_t)m * ldc + n]) = outv;
    }
}

// ---------------- prep kernels ----------------
__global__ void prep_weights_kernel(
    const float* __restrict__ Wdec, const float* __restrict__ bdec,
    const float* __restrict__ Wbeta, const float* __restrict__ bbeta,
    const float* __restrict__ Wih, const float* __restrict__ Whh,
    const float* __restrict__ bih, const float* __restrict__ bhh,
    const float* __restrict__ Winith, const float* __restrict__ binith,
    const float* __restrict__ Winitc, const float* __restrict__ binitc)
{
    const int stride = gridDim.x * blockDim.x;
    const int i0 = blockIdx.x * blockDim.x + threadIdx.x;
    for (int i = i0; i < 512 * 512; i += stride) {
        g_Wab[i] = Wdec[i];
        g_Wab[512 * 512 + i] = Wbeta[i];
        g_Winit[i] = Winith[i];
        g_Winit[512 * 512 + i] = Winitc[i];
    }
    for (int i = i0; i < 512; i += stride) {
        g_bab[i] = bdec[i];       g_bab[512 + i] = bbeta[i];
        g_binit[i] = binith[i];   g_binit[512 + i] = binitc[i];
    }
    for (int i = i0; i < 2048 * 1280; i += stride) {
        int nrow = i / 1280, k = i - nrow * 1280;
        g_Wlstm[i] = (k < 768) ? Wih[nrow * 768 + k] : Whh[nrow * 512 + (k - 768)];
    }
    for (int i = i0; i < 2048; i += stride) g_blstm[i] = bih[i] + bhh[i];
}

__global__ void build_list_kernel(const int* __restrict__ lens)
{
    __shared__ int offs[64];
    const int b = threadIdx.x;
    if (b == 0) {
        int o = 0;
        for (int i = 0; i < B_; i++) { offs[i] = o; o += lens[i] - 1; }
        g_nact = o;
    }
    __syncthreads();
    if (b < B_) {
        const int o = offs[b];
        const int n = lens[b] - 1;
        for (int t = 0; t < n; t++) g_list[o + t] = (t << 6) | b;
    }
}

__global__ void zerofill_kernel(const int* __restrict__ lens, float* __restrict__ out)
{
    const int b = blockIdx.x / T_;
    const int t = blockIdx.x % T_;
    if (t < lens[b] - 1) return;
    float4 z; z.x = z.y = z.z = z.w = 0.f;
    float4* o = reinterpret_cast<float4*>(out + ((size_t)b * T_ + t) * V_);
    for (int i = threadIdx.x; i < V_ / 4; i += blockDim.x) o[i] = z;
}

__global__ void meanenc_kernel(const float* __restrict__ EO)
{
    const int wg = (blockIdx.x * blockDim.x + threadIdx.x) >> 5;
    const int lane = threadIdx.x & 31;
    if (wg >= B_ * ENC_) return;
    const float* row = EO + (size_t)wg * P_;
    float s = 0.f;
    for (int p = lane; p < P_; p += 32) s += row[p];
#pragma unroll
    for (int o = 16; o; o >>= 1) s += __shfl_xor_sync(0xffffffffu, s, o);
    if (!lane) g_meanenc[wg] = s * (1.0f / P_);
}

// ---------------- launch ----------------
extern "C" void kernel_launch(void* const* d_in, const int* in_sizes, int n_in,
                              void* d_out, int out_size)
{
    const float* EO        = (const float*)d_in[0];
    const int*   caps      = (const int*)  d_in[1];
    const int*   lens      = (const int*)  d_in[2];
    const float* W_enc_att = (const float*)d_in[3];
    const float* b_enc_att = (const float*)d_in[4];
    const float* W_dec_att = (const float*)d_in[5];
    const float* b_dec_att = (const float*)d_in[6];
    const float* w_full    = (const float*)d_in[7];
    const float* b_full    = (const float*)d_in[8];
    const float* emb       = (const float*)d_in[9];
    const float* W_ih      = (const float*)d_in[10];
    const float* W_hh      = (const float*)d_in[11];
    const float* b_ih      = (const float*)d_in[12];
    const float* b_hh      = (const float*)d_in[13];
    const float* W_init_h  = (const float*)d_in[14];
    const float* b_init_h  = (const float*)d_in[15];
    const float* W_init_c  = (const float*)d_in[16];
    const float* b_init_c  = (const float*)d_in[17];
    const float* W_beta    = (const float*)d_in[18];
    const float* b_beta    = (const float*)d_in[19];
    const float* W_fc      = (const float*)d_in[20];
    const float* b_fc      = (const float*)d_in[21];
    float* out = (float*)d_out;

    float *state, *meanenc, *Winit, *binit;
    cudaGetSymbolAddress((void**)&state,   g_state);
    cudaGetSymbolAddress((void**)&meanenc, g_meanenc);
    cudaGetSymbolAddress((void**)&Winit,   g_Winit);
    cudaGetSymbolAddress((void**)&binit,   g_binit);

    // ---- one-time prep ----
    prep_weights_kernel<<<512, 256>>>(W_dec_att, b_dec_att, W_beta, b_beta,
                                      W_ih, W_hh, b_ih, b_hh,
                                      W_init_h, b_init_h, W_init_c, b_init_c);
    build_list_kernel<<<1, 64>>>(lens);
    zerofill_kernel<<<B_ * T_, 256>>>(lens, out);
    meanenc_kernel<<<4096, 256>>>(EO);
    gemm64_kernel<<<dim3(16, 1), 256>>>(meanenc, 512, Winit, 512, binit,
                                        state, 1024, 512);
    // att1 = enc @ W_enc_att^T + b (reads EO transposed during staging)
    att1_gemm_kernel<<<dim3(4, 128), 256>>>(EO, W_enc_att, b_enc_att);

    // ---- full decode recurrence in ONE persistent kernel ----
    step_kernel<<<NB_, 256>>>(EO, emb, caps, w_full, b_full);

    // ---- all predictions in one big GEMM over active rows ----
    fc_gemm_kernel<<<dim3(125, 16), 256>>>(W_fc, b_fc, out);
}